// round 5
// baseline (speedup 1.0000x reference)
#include <cuda_runtime.h>
#include <cuda_fp16.h>
#include <cstdint>

// Problem dims (fixed): X:(B,N), boundaries:(N,K+1), weight:(N,K,E), bias:(N,E)
#define BDIM 4096
#define NDIM 64
#define KDIM 128
#define EDIM 512
#define EPS_F 1e-8f

// Prefix table T[n][k][e] (fp16): T[n][k][e] = bias[n][e] + sum_{j<k} w[n][j][e]
// out[b][n][e] = relu( lerp(T[n][bidx], T[n][bidx+1], frac) )
__device__ __half g_T16[(size_t)NDIM * (KDIM + 1) * EDIM];
// Per-(b,n) precomputed (frac, bidx), indexed b*N+n.
__device__ float2 g_SF[(size_t)BDIM * NDIM];

#define ETILE 64
#define PREFIX_BLOCKS (NDIM * (EDIM / ETILE))          // 512
#define SEARCH_BLOCKS ((BDIM * NDIM) / 256)            // 1024

// ---------------------------------------------------------------------------
// Setup (fused):
//  blocks [0,512): prefix table via SMEM blocked scan. Block = (n, 64-e tile).
//    Coalesced 32KB tile load -> 4 chunk-sums per e column -> bases -> scan.
//    Reads weight exactly once (16MB total), no redundancy.
//  blocks [512,1536): one binary search per thread over all (b,n), -> g_SF.
// ---------------------------------------------------------------------------
__global__ void setup_kernel(const float* __restrict__ X,
                             const float* __restrict__ bnd,
                             const float* __restrict__ weight,
                             const float* __restrict__ bias) {
    if (blockIdx.x < PREFIX_BLOCKS) {
        __shared__ float tile[KDIM][ETILE + 1];        // +1 pad: conflict-free
        __shared__ float csum[4][ETILE];

        const int n  = blockIdx.x / (EDIM / ETILE);
        const int e0 = (blockIdx.x % (EDIM / ETILE)) * ETILE;
        const int tid = threadIdx.x;

        // Coalesced tile load: 128 rows x 64 floats (256B/row)
        const float* wp = weight + (size_t)n * KDIM * EDIM + e0;
        for (int i = tid; i < KDIM * ETILE; i += 256) {
            int k = i >> 6, col = i & 63;
            tile[k][col] = wp[(size_t)k * EDIM + col];
        }
        __syncthreads();

        const int col = tid & 63;      // e column
        const int c   = tid >> 6;      // k-chunk 0..3 (warps stay within one c)

        float s = 0.f;
#pragma unroll
        for (int j = 0; j < 32; j++) s += tile[32 * c + j][col];
        csum[c][col] = s;
        __syncthreads();

        float acc = bias[n * EDIM + e0 + col];
#pragma unroll
        for (int cc = 0; cc < 3; cc++)
            if (cc < c) acc += csum[cc][col];

        __half* Tp = g_T16 + ((size_t)n * (KDIM + 1)) * EDIM + e0 + col;
#pragma unroll
        for (int j = 0; j < 32; j++) {
            int k = 32 * c + j;
            Tp[(size_t)k * EDIM] = __float2half_rn(acc);
            acc += tile[k][col];
        }
        if (c == 3)
            Tp[(size_t)KDIM * EDIM] = __float2half_rn(acc);
    } else {
        int i = (blockIdx.x - PREFIX_BLOCKS) * blockDim.x + threadIdx.x; // b*N+n
        int n = i & (NDIM - 1);
        const float x = X[i];
        const float* bn = bnd + (size_t)n * (KDIM + 1);

        int lo = 0, len = KDIM - 1;
        while (len > 0) {
            int half = len >> 1;
            bool pred = __ldg(&bn[1 + lo + half]) < x;
            lo  += pred ? (half + 1) : 0;
            len  = pred ? (len - half - 1) : half;
        }
        const float s  = __ldg(&bn[lo]);
        const float eb = __ldg(&bn[lo + 1]);
        const float frac = (x - s) / (eb - s + EPS_F);
        g_SF[i] = make_float2(frac, __int_as_float(lo));
    }
}

// ---------------------------------------------------------------------------
// Gather: block = (b, 8 consecutive n). Warp w handles row (b, n0+w): loads
// (frac,lo), front-batches 4 table LDG.128, lerps in fp32, STS into its 2KB
// SMEM slot. The 8 rows are CONTIGUOUS in GMEM -> one 16KB cp.async.bulk
// per block (8x fewer TMA ops than per-warp stores, larger DRAM bursts).
// ---------------------------------------------------------------------------
__global__ void gather_kernel(float* __restrict__ out) {
    __shared__ float4 sm[8][EDIM / 4];                 // 8 x 2KB = 16KB

    const int lane = threadIdx.x & 31;
    const int warp = threadIdx.x >> 5;
    const int b  = blockIdx.x;
    const int n0 = blockIdx.y * 8;
    const int n  = n0 + warp;

    const float2 sf = __ldg(&g_SF[(size_t)b * NDIM + n]);
    const float frac = sf.x;
    const int   lo   = __float_as_int(sf.y);

    const uint4* T0 = (const uint4*)(g_T16 + ((size_t)n * (KDIM + 1) + lo) * EDIM);
    const uint4* T1 = T0 + (EDIM / 8);

    uint4 a0 = __ldg(&T0[lane]);
    uint4 c0 = __ldg(&T1[lane]);
    uint4 a1 = __ldg(&T0[lane + 32]);
    uint4 c1 = __ldg(&T1[lane + 32]);

#pragma unroll
    for (int j = 0; j < 2; j++) {
        const uint4& a  = j ? a1 : a0;
        const uint4& cc = j ? c1 : c0;
        const unsigned* ap = &a.x;
        const unsigned* cp = &cc.x;
        float4 r0, r1;
#pragma unroll
        for (int q = 0; q < 4; q++) {
            float2 av = __half22float2(*(const __half2*)&ap[q]);
            float2 cv = __half22float2(*(const __half2*)&cp[q]);
            float v0 = fmaxf(fmaf(frac, cv.x - av.x, av.x), 0.0f);
            float v1 = fmaxf(fmaf(frac, cv.y - av.y, av.y), 0.0f);
            if (q == 0)      { r0.x = v0; r0.y = v1; }
            else if (q == 1) { r0.z = v0; r0.w = v1; }
            else if (q == 2) { r1.x = v0; r1.y = v1; }
            else             { r1.z = v0; r1.w = v1; }
        }
        const int i = lane + 32 * j;
        sm[warp][2 * i]     = r0;
        sm[warp][2 * i + 1] = r1;
    }

    __syncthreads();

    if (threadIdx.x == 0) {
        // 8 contiguous output rows: one 16KB bulk async store
        float* gdst = out + ((size_t)b * NDIM + n0) * EDIM;
        uint32_t saddr;
        asm("{ .reg .u64 t; cvta.to.shared.u64 t, %1; cvt.u32.u64 %0, t; }"
            : "=r"(saddr) : "l"(&sm[0][0]));
        asm volatile("fence.proxy.async.shared::cta;" ::: "memory");
        asm volatile(
            "cp.async.bulk.global.shared::cta.bulk_group [%0], [%1], %2;"
            :: "l"(gdst), "r"(saddr), "r"((int)(8 * EDIM * 4)) : "memory");
        asm volatile("cp.async.bulk.commit_group;" ::: "memory");
        asm volatile("cp.async.bulk.wait_group 0;" ::: "memory");
    }
}

extern "C" void kernel_launch(void* const* d_in, const int* in_sizes, int n_in,
                              void* d_out, int out_size) {
    const float* X      = (const float*)d_in[0];   // (B, N)
    const float* bnd    = (const float*)d_in[1];   // (N, K+1)
    const float* weight = (const float*)d_in[2];   // (N, K, E)
    const float* bias   = (const float*)d_in[3];   // (N, E)
    float* out = (float*)d_out;                    // (B, N, E)

    setup_kernel<<<PREFIX_BLOCKS + SEARCH_BLOCKS, 256>>>(X, bnd, weight, bias);

    dim3 grid(BDIM, NDIM / 8);
    gather_kernel<<<grid, 256>>>(out);
}